// round 9
// baseline (speedup 1.0000x reference)
#include <cuda_runtime.h>

// loss = mean_b( ||sum_n att_n||^2 - sum_n ||att_n||^2 ),  att_n = x_n / max(||x_n||, 1e-12)
// B=128, N=64, D=2048.
// 128 CTAs x 512 threads (16 warps = 8 pairs). Each pair owns 8 rows; within a
// row each warp loads a HALF row (8 float4/lane, 32 regs) and the two halves'
// sumsq are combined through smem + a named pair barrier (bar.sync id,64).
// Each warp accumulates a half-width s partial (8 float4/lane). No full-block
// barriers until the epilogue. Cross-batch mean fused via last-block ticket.

#define B_BATCH 128
#define N_ROWS  64
#define D_COLS  2048          // 512 float4 per row
#define NTHREADS 512
#define NPAIR   8
#define EPSF    1e-12f

static __device__ double g_batch_loss[B_BATCH];
static __device__ unsigned int g_done = 0;

__global__ void __launch_bounds__(NTHREADS, 1)
loss_fused_kernel(const float* __restrict__ in, float* __restrict__ out)
{
    __shared__ float  pairsum[NPAIR][2][2];  // [pair][row parity][half]
    __shared__ float4 sbuf[NPAIR][128];      // 16 KB publish area
    __shared__ double dsm[16 + NPAIR];       // [0..15]=ssq per warp, [16..23]=diag per pair
    __shared__ unsigned int s_ticket;

    const int tid  = threadIdx.x;
    const int wid  = tid >> 5;
    const int lane = tid & 31;
    const int pair = wid >> 1;
    const int half = wid & 1;
    const int b    = blockIdx.x;

    const float4* __restrict__ base =
        (const float4*)(in + (size_t)b * (N_ROWS * D_COLS));

    // warp's half-width s partial: lane covers float4 idx half*256 + j*32 + lane
    float4 s[8];
#pragma unroll
    for (int j = 0; j < 8; ++j) s[j] = make_float4(0.f, 0.f, 0.f, 0.f);

    double diag = 0.0;   // pair's half-0 warp, lane 0

    // pair owns rows {pair, pair+8, ..., pair+56}
#pragma unroll
    for (int k = 0; k < 8; ++k) {
        const int row = pair + k * NPAIR;
        const float4* __restrict__ rp = base + row * 512 + half * 256;

        // batched half-row load (8 independent LDG.128)
        float4 d[8];
#pragma unroll
        for (int j = 0; j < 8; ++j) d[j] = rp[j * 32 + lane];

        float a0 = 0.f, a1 = 0.f, a2 = 0.f, a3 = 0.f;
#pragma unroll
        for (int j = 0; j < 8; ++j) {
            a0 = fmaf(d[j].x, d[j].x, a0);
            a1 = fmaf(d[j].y, d[j].y, a1);
            a2 = fmaf(d[j].z, d[j].z, a2);
            a3 = fmaf(d[j].w, d[j].w, a3);
        }
        float sq = (a0 + a1) + (a2 + a3);
#pragma unroll
        for (int o = 16; o > 0; o >>= 1)
            sq += __shfl_xor_sync(0xffffffffu, sq, o);

        if (lane == 0) pairsum[pair][k & 1][half] = sq;
        // pair-scoped barrier (ids 1..8; id 0 left for __syncthreads)
        asm volatile("bar.sync %0, %1;" :: "r"(pair + 1), "n"(64) : "memory");

        float tot = pairsum[pair][k & 1][0] + pairsum[pair][k & 1][1];
        float inv = 1.0f / fmaxf(sqrtf(tot), EPSF);

        if (half == 0 && lane == 0)
            diag += (double)tot * ((double)inv * (double)inv);

        // scaled accumulate from registers (no memory traffic)
#pragma unroll
        for (int j = 0; j < 8; ++j) {
            s[j].x = fmaf(d[j].x, inv, s[j].x);
            s[j].y = fmaf(d[j].y, inv, s[j].y);
            s[j].z = fmaf(d[j].z, inv, s[j].z);
            s[j].w = fmaf(d[j].w, inv, s[j].w);
        }
    }

    if (half == 0 && lane == 0) dsm[16 + pair] = diag;

    // ---- epilogue: reduce s. For each (half h, chunk c): the 8 warps of that
    // half publish 128 float4 each; threads 0..127 combine and square. ----
    double ssq = 0.0;
#pragma unroll
    for (int h = 0; h < 2; ++h) {
#pragma unroll
        for (int c = 0; c < 2; ++c) {
            __syncthreads();
            if (half == h) {
#pragma unroll
                for (int jj = 0; jj < 4; ++jj)
                    sbuf[pair][jj * 32 + lane] = s[c * 4 + jj];
            }
            __syncthreads();
            if (tid < 128) {
                float4 tot = sbuf[0][tid];
#pragma unroll
                for (int p = 1; p < NPAIR; ++p) {
                    float4 q = sbuf[p][tid];
                    tot.x += q.x; tot.y += q.y; tot.z += q.z; tot.w += q.w;
                }
                ssq += (double)tot.x * (double)tot.x;
                ssq += (double)tot.y * (double)tot.y;
                ssq += (double)tot.z * (double)tot.z;
                ssq += (double)tot.w * (double)tot.w;
            }
        }
    }

    // block-reduce ssq (threads >=128 contribute 0)
#pragma unroll
    for (int o = 16; o > 0; o >>= 1)
        ssq += __shfl_xor_sync(0xffffffffu, ssq, o);
    if (lane == 0) dsm[wid] = ssq;
    __syncthreads();

    if (tid == 0) {
        double S = 0.0, Dg = 0.0;
#pragma unroll
        for (int w = 0; w < 16; ++w) S += dsm[w];
#pragma unroll
        for (int p = 0; p < NPAIR; ++p) Dg += dsm[16 + p];
        g_batch_loss[b] = S - Dg;
        __threadfence();
        s_ticket = atomicAdd(&g_done, 1u);
    }
    __syncthreads();

    // last finishing block: deterministic fixed-order mean over batches
    if (s_ticket == B_BATCH - 1) {
        double v = (tid < B_BATCH) ? g_batch_loss[tid] : 0.0;
#pragma unroll
        for (int o = 16; o > 0; o >>= 1)
            v += __shfl_xor_sync(0xffffffffu, v, o);
        if (lane == 0) dsm[wid] = v;
        __syncthreads();
        if (tid == 0) {
            double t = 0.0;
#pragma unroll
            for (int w = 0; w < 4; ++w) t += dsm[w];   // batches live in warps 0..3
            out[0] = (float)(t / (double)B_BATCH);
            g_done = 0;   // self-reset for graph replay
        }
    }
}

extern "C" void kernel_launch(void* const* d_in, const int* in_sizes, int n_in,
                              void* d_out, int out_size)
{
    (void)in_sizes; (void)n_in; (void)out_size;
    const float* in = (const float*)d_in[0];
    float* out = (float*)d_out;

    loss_fused_kernel<<<B_BATCH, NTHREADS>>>(in, out);
}

// round 11
// speedup vs baseline: 1.2280x; 1.2280x over previous
#include <cuda_runtime.h>

// loss = mean_b( ||sum_n att_n||^2 - sum_n ||att_n||^2 ),  att_n = x_n / max(||x_n||, 1e-12)
// B=128, N=64, D=2048.
// Grid 256 CTAs x 256 threads, 2 CTAs per batch (rows split 32/32), 2 CTAs
// co-resident per SM -> all 148 SMs busy, tails overlap across CTAs.
// Inner loop = R1 proven pattern: STREAMING sumsq pass (short live ranges, no
// register-held burst) + L1 re-read accumulate into warp-wide s[16].
// Pair combine via per-batch ticket; global mean via last-batch ticket.

#define B_BATCH 128
#define N_ROWS  64
#define D_COLS  2048          // 512 float4 per row
#define NWARP   8
#define NTHREADS 256
#define NCTA    (2 * B_BATCH)
#define EPSF    1e-12f

static __device__ float        g_s[NCTA * D_COLS];     // 2 MB s-partials
static __device__ double       g_diag[NCTA];
static __device__ double       g_batch_loss[B_BATCH];
static __device__ unsigned int g_pair_done[B_BATCH];   // zero-init, self-reset
static __device__ unsigned int g_done = 0;

__global__ void __launch_bounds__(NTHREADS, 2)
loss_fused_kernel(const float* __restrict__ in, float* __restrict__ out)
{
    __shared__ float4 sbuf[NWARP][128];   // 16 KB publish area
    __shared__ double dsm[NWARP];
    __shared__ unsigned int s_t1, s_t2;

    const int tid  = threadIdx.x;
    const int wid  = tid >> 5;
    const int lane = tid & 31;
    const int cta  = blockIdx.x;
    const int b    = cta >> 1;
    const int half = cta & 1;             // which 32-row half of the batch

    const float4* __restrict__ base =
        (const float4*)(in + (size_t)b * (N_ROWS * D_COLS));

    // warp-wide s partial over all 2048 columns
    float4 s[16];
#pragma unroll
    for (int j = 0; j < 16; ++j) s[j] = make_float4(0.f, 0.f, 0.f, 0.f);

    double diag = 0.0;   // lane 0 only

    // warp wid owns rows half*32 + {wid, wid+8, wid+16, wid+24}
#pragma unroll
    for (int k = 0; k < 4; ++k) {
        const float4* __restrict__ row =
            base + (half * 32 + wid + k * NWARP) * (D_COLS / 4);

        // pass A: STREAMING sumsq (loads consumed immediately, not held)
        float a0 = 0.f, a1 = 0.f, a2 = 0.f, a3 = 0.f;
#pragma unroll
        for (int j = 0; j < 16; ++j) {
            float4 v = row[j * 32 + lane];
            a0 = fmaf(v.x, v.x, a0);
            a1 = fmaf(v.y, v.y, a1);
            a2 = fmaf(v.z, v.z, a2);
            a3 = fmaf(v.w, v.w, a3);
        }
        float sq = (a0 + a1) + (a2 + a3);
#pragma unroll
        for (int o = 16; o > 0; o >>= 1)
            sq += __shfl_xor_sync(0xffffffffu, sq, o);

        float inv = 1.0f / fmaxf(sqrtf(sq), EPSF);

        if (lane == 0)
            diag += (double)sq * ((double)inv * (double)inv);

        // pass B: re-read row (L1 hit) and accumulate s
#pragma unroll
        for (int j = 0; j < 16; ++j) {
            float4 v = row[j * 32 + lane];
            s[j].x = fmaf(v.x, inv, s[j].x);
            s[j].y = fmaf(v.y, inv, s[j].y);
            s[j].z = fmaf(v.z, inv, s[j].z);
            s[j].w = fmaf(v.w, inv, s[j].w);
        }
    }

    if (lane == 0) dsm[wid] = diag;

    // ---- epilogue: reduce s across 8 warps, write CTA s-partial to global ----
    float4* __restrict__ gs4 = (float4*)(g_s + (size_t)cta * D_COLS);
#pragma unroll
    for (int c = 0; c < 4; ++c) {
        __syncthreads();
#pragma unroll
        for (int jj = 0; jj < 4; ++jj)
            sbuf[wid][jj * 32 + lane] = s[c * 4 + jj];
        __syncthreads();
        if (tid < 128) {
            float4 tot = sbuf[0][tid];
#pragma unroll
            for (int w = 1; w < NWARP; ++w) {
                float4 p = sbuf[w][tid];
                tot.x += p.x; tot.y += p.y; tot.z += p.z; tot.w += p.w;
            }
            gs4[c * 128 + tid] = tot;
        }
    }
    __syncthreads();

    if (tid == 0) {
        double Dg = 0.0;
#pragma unroll
        for (int w = 0; w < NWARP; ++w) Dg += dsm[w];
        g_diag[cta] = Dg;
        __threadfence();
        s_t1 = atomicAdd(&g_pair_done[b], 1u);
    }
    __syncthreads();

    // second finisher of the pair combines the two halves
    if (s_t1 == 1) {
        const float* __restrict__ sA = g_s + (size_t)(2 * b)     * D_COLS;
        const float* __restrict__ sB = g_s + (size_t)(2 * b + 1) * D_COLS;
        double acc = 0.0;
#pragma unroll
        for (int i = 0; i < 8; ++i) {
            int idx = tid + i * NTHREADS;
            float v = sA[idx] + sB[idx];
            acc += (double)v * (double)v;
        }
#pragma unroll
        for (int o = 16; o > 0; o >>= 1)
            acc += __shfl_xor_sync(0xffffffffu, acc, o);
        if (lane == 0) dsm[wid] = acc;
        __syncthreads();

        if (tid == 0) {
            double S = 0.0;
#pragma unroll
            for (int w = 0; w < NWARP; ++w) S += dsm[w];
            g_batch_loss[b] = S - (g_diag[2 * b] + g_diag[2 * b + 1]);
            g_pair_done[b] = 0;            // self-reset for graph replay
            __threadfence();
            s_t2 = atomicAdd(&g_done, 1u);
        }
        __syncthreads();

        // last finishing combiner: deterministic fixed-order mean over batches
        if (s_t2 == B_BATCH - 1) {
            double v = (tid < B_BATCH) ? g_batch_loss[tid] : 0.0;
#pragma unroll
            for (int o = 16; o > 0; o >>= 1)
                v += __shfl_xor_sync(0xffffffffu, v, o);
            if (lane == 0) dsm[wid] = v;
            __syncthreads();
            if (tid == 0) {
                double t = 0.0;
#pragma unroll
                for (int w = 0; w < 4; ++w) t += dsm[w];  // 128 batches = warps 0..3
                out[0] = (float)(t / (double)B_BATCH);
                g_done = 0;                // self-reset for graph replay
            }
        }
    }
}

extern "C" void kernel_launch(void* const* d_in, const int* in_sizes, int n_in,
                              void* d_out, int out_size)
{
    (void)in_sizes; (void)n_in; (void)out_size;
    const float* in = (const float*)d_in[0];
    float* out = (float*)d_out;

    loss_fused_kernel<<<NCTA, NTHREADS>>>(in, out);
}

// round 16
// speedup vs baseline: 1.5209x; 1.2385x over previous
#include <cuda_runtime.h>

// loss = mean_b( ||sum_n att_n||^2 - sum_n ||att_n||^2 ),  att_n = x_n / max(||x_n||, 1e-12)
// B=128, N=64, D=2048.
// 128 CTAs x 256 threads (8 warps). Software-pipelined DOUBLE register buffer:
// row k+1's 16 LDG.128 issue before row k's reduce/accumulate tail, no WAR
// hazard (alternating dA/dB). inv via rsqrtf(max(sq,eps^2)) == 1/max(norm,eps).
// Epilogue + fused cross-batch mean identical to the proven R7 kernel.

#define B_BATCH 128
#define N_ROWS  64
#define D_COLS  2048          // 512 float4 per row
#define NWARP   8
#define NTHREADS 256
#define EPS2F   1e-24f

static __device__ double g_batch_loss[B_BATCH];
static __device__ unsigned int g_done = 0;

// process one register-resident row buffer: sumsq -> inv -> diag -> s accumulate
__device__ __forceinline__ void process_row(const float4 (&d)[16], float4 (&s)[16],
                                            double& diag, int lane)
{
    float a0 = 0.f, a1 = 0.f, a2 = 0.f, a3 = 0.f;
#pragma unroll
    for (int j = 0; j < 16; ++j) {
        a0 = fmaf(d[j].x, d[j].x, a0);
        a1 = fmaf(d[j].y, d[j].y, a1);
        a2 = fmaf(d[j].z, d[j].z, a2);
        a3 = fmaf(d[j].w, d[j].w, a3);
    }
    float sq = (a0 + a1) + (a2 + a3);
#pragma unroll
    for (int o = 16; o > 0; o >>= 1)
        sq += __shfl_xor_sync(0xffffffffu, sq, o);

    // 1/max(sqrt(sq),1e-12) == rsqrt(max(sq,1e-24))
    float inv = rsqrtf(fmaxf(sq, EPS2F));

    if (lane == 0)
        diag += (double)sq * ((double)inv * (double)inv);

#pragma unroll
    for (int j = 0; j < 16; ++j) {
        s[j].x = fmaf(d[j].x, inv, s[j].x);
        s[j].y = fmaf(d[j].y, inv, s[j].y);
        s[j].z = fmaf(d[j].z, inv, s[j].z);
        s[j].w = fmaf(d[j].w, inv, s[j].w);
    }
}

__device__ __forceinline__ void load_row(float4 (&d)[16],
                                         const float4* __restrict__ row, int lane)
{
#pragma unroll
    for (int j = 0; j < 16; ++j) d[j] = row[j * 32 + lane];
}

__global__ void __launch_bounds__(NTHREADS, 1)
loss_fused_kernel(const float* __restrict__ in, float* __restrict__ out)
{
    __shared__ float4 sbuf[NWARP][128];   // 16 KB publish area
    __shared__ double dsm[2 * NWARP];     // [0..7]=ssq per warp, [8..15]=diag per warp
    __shared__ unsigned int s_ticket;

    const int tid  = threadIdx.x;
    const int wid  = tid >> 5;
    const int lane = tid & 31;
    const int b    = blockIdx.x;

    const float4* __restrict__ base =
        (const float4*)(in + (size_t)b * (N_ROWS * D_COLS));

    float4 s[16];
#pragma unroll
    for (int j = 0; j < 16; ++j) s[j] = make_float4(0.f, 0.f, 0.f, 0.f);

    double diag = 0.0;   // lane 0 only

    float4 dA[16], dB[16];

    // warp wid owns rows wid + r*8, r = 0..7, pipelined in A/B pairs
    load_row(dA, base + (wid + 0 * NWARP) * 512, lane);

#pragma unroll
    for (int k = 0; k < 4; ++k) {
        // prefetch odd row into dB, then process dA (its loads drain meanwhile)
        load_row(dB, base + (wid + (2 * k + 1) * NWARP) * 512, lane);
        process_row(dA, s, diag, lane);

        // prefetch next even row into dA (skip on last pair), process dB
        if (k < 3)
            load_row(dA, base + (wid + (2 * k + 2) * NWARP) * 512, lane);
        process_row(dB, s, diag, lane);
    }

    if (lane == 0) dsm[NWARP + wid] = diag;

    // ---- epilogue: reduce s across the 8 warps in 4 column chunks ----
    double ssq = 0.0;
#pragma unroll
    for (int c = 0; c < 4; ++c) {
        __syncthreads();
#pragma unroll
        for (int jj = 0; jj < 4; ++jj)
            sbuf[wid][jj * 32 + lane] = s[c * 4 + jj];
        __syncthreads();
        if (tid < 128) {
            float4 tot = sbuf[0][tid];
#pragma unroll
            for (int w = 1; w < NWARP; ++w) {
                float4 p = sbuf[w][tid];
                tot.x += p.x; tot.y += p.y; tot.z += p.z; tot.w += p.w;
            }
            ssq += (double)tot.x * (double)tot.x;
            ssq += (double)tot.y * (double)tot.y;
            ssq += (double)tot.z * (double)tot.z;
            ssq += (double)tot.w * (double)tot.w;
        }
    }

    // block-reduce ssq (upper 128 threads contribute 0)
#pragma unroll
    for (int o = 16; o > 0; o >>= 1)
        ssq += __shfl_xor_sync(0xffffffffu, ssq, o);
    if (lane == 0) dsm[wid] = ssq;
    __syncthreads();

    if (tid == 0) {
        double S = 0.0, Dg = 0.0;
#pragma unroll
        for (int w = 0; w < NWARP; ++w) { S += dsm[w]; Dg += dsm[NWARP + w]; }
        g_batch_loss[b] = S - Dg;
        __threadfence();
        s_ticket = atomicAdd(&g_done, 1u);
    }
    __syncthreads();

    // last finishing block: deterministic fixed-order mean over batches
    if (s_ticket == B_BATCH - 1) {
        double v = (tid < B_BATCH) ? g_batch_loss[tid] : 0.0;
#pragma unroll
        for (int o = 16; o > 0; o >>= 1)
            v += __shfl_xor_sync(0xffffffffu, v, o);
        if (lane == 0) dsm[wid] = v;
        __syncthreads();
        if (tid == 0) {
            double t = 0.0;
#pragma unroll
            for (int w = 0; w < 4; ++w) t += dsm[w];   // batches live in warps 0..3
            out[0] = (float)(t / (double)B_BATCH);
            g_done = 0;   // self-reset for graph replay
        }
    }
}

extern "C" void kernel_launch(void* const* d_in, const int* in_sizes, int n_in,
                              void* d_out, int out_size)
{
    (void)in_sizes; (void)n_in; (void)out_size;
    const float* in = (const float*)d_in[0];
    float* out = (float*)d_out;

    loss_fused_kernel<<<B_BATCH, NTHREADS>>>(in, out);
}

// round 17
// speedup vs baseline: 1.5435x; 1.0149x over previous
#include <cuda_runtime.h>

// loss = mean_b( ||sum_n att_n||^2 - sum_n ||att_n||^2 ),  att_n = x_n / max(||x_n||, 1e-12)
// B=128, N=64, D=2048.
// 128 CTAs x 256 threads (8 warps). Distance-1 STREAM pipeline, no held row
// buffers: iteration k interleaves row k+1's DRAM sumsq stream with row k's
// L1 re-read accumulate (inv_k known). Register peak ~190 (s[16] + transient
// window), so ptxas keeps full MLP. Epilogue + cross-batch ticket as in R7.

#define B_BATCH 128
#define N_ROWS  64
#define D_COLS  2048          // 512 float4 per row
#define NWARP   8
#define NTHREADS 256
#define EPS2F   1e-24f

static __device__ double g_batch_loss[B_BATCH];
static __device__ unsigned int g_done = 0;

__device__ __forceinline__ float warp_reduce_add(float v)
{
#pragma unroll
    for (int o = 16; o > 0; o >>= 1)
        v += __shfl_xor_sync(0xffffffffu, v, o);
    return v;
}

__global__ void __launch_bounds__(NTHREADS, 1)
loss_fused_kernel(const float* __restrict__ in, float* __restrict__ out)
{
    __shared__ float4 sbuf[NWARP][128];   // 16 KB publish area
    __shared__ double dsm[2 * NWARP];     // [0..7]=ssq per warp, [8..15]=diag per warp
    __shared__ unsigned int s_ticket;

    const int tid  = threadIdx.x;
    const int wid  = tid >> 5;
    const int lane = tid & 31;
    const int b    = blockIdx.x;

    const float4* __restrict__ base =
        (const float4*)(in + (size_t)b * (N_ROWS * D_COLS));

    float4 s[16];
#pragma unroll
    for (int j = 0; j < 16; ++j) s[j] = make_float4(0.f, 0.f, 0.f, 0.f);

    double diag = 0.0;   // lane 0 only

    // ---- prologue: stream sumsq of row (wid), get inv_0 ----
    float inv;
    {
        const float4* __restrict__ r0 = base + wid * 512;
        float p0 = 0.f, p1 = 0.f, p2 = 0.f, p3 = 0.f;
#pragma unroll
        for (int j = 0; j < 16; ++j) {
            float4 v = r0[j * 32 + lane];
            p0 = fmaf(v.x, v.x, p0);
            p1 = fmaf(v.y, v.y, p1);
            p2 = fmaf(v.z, v.z, p2);
            p3 = fmaf(v.w, v.w, p3);
        }
        float sq = warp_reduce_add((p0 + p1) + (p2 + p3));
        inv = rsqrtf(fmaxf(sq, EPS2F));         // == 1/max(sqrt(sq),1e-12)
        if (lane == 0)
            diag += (double)sq * ((double)inv * (double)inv);
    }

    // ---- main pipeline: iteration k accumulates row k (L1 re-read, inv known)
    //      while streaming row k+1's DRAM sumsq ----
#pragma unroll
    for (int k = 0; k < 8; ++k) {
        const float4* __restrict__ cur = base + (wid + k * NWARP) * 512;

        if (k < 7) {
            const float4* __restrict__ nxt = base + (wid + (k + 1) * NWARP) * 512;
            float a0 = 0.f, a1 = 0.f, a2 = 0.f, a3 = 0.f;
#pragma unroll
            for (int j = 0; j < 16; ++j) {
                float4 vn = nxt[j * 32 + lane];    // DRAM stream (next row)
                float4 vc = cur[j * 32 + lane];    // L1 hit (current row)
                a0 = fmaf(vn.x, vn.x, a0);
                a1 = fmaf(vn.y, vn.y, a1);
                a2 = fmaf(vn.z, vn.z, a2);
                a3 = fmaf(vn.w, vn.w, a3);
                s[j].x = fmaf(vc.x, inv, s[j].x);
                s[j].y = fmaf(vc.y, inv, s[j].y);
                s[j].z = fmaf(vc.z, inv, s[j].z);
                s[j].w = fmaf(vc.w, inv, s[j].w);
            }
            float sq = warp_reduce_add((a0 + a1) + (a2 + a3));
            float ninv = rsqrtf(fmaxf(sq, EPS2F));
            if (lane == 0)
                diag += (double)sq * ((double)ninv * (double)ninv);
            inv = ninv;
        } else {
            // last row: accumulate only (L1 hit)
#pragma unroll
            for (int j = 0; j < 16; ++j) {
                float4 vc = cur[j * 32 + lane];
                s[j].x = fmaf(vc.x, inv, s[j].x);
                s[j].y = fmaf(vc.y, inv, s[j].y);
                s[j].z = fmaf(vc.z, inv, s[j].z);
                s[j].w = fmaf(vc.w, inv, s[j].w);
            }
        }
    }

    if (lane == 0) dsm[NWARP + wid] = diag;

    // ---- epilogue: reduce s across the 8 warps in 4 column chunks ----
    double ssq = 0.0;
#pragma unroll
    for (int c = 0; c < 4; ++c) {
        __syncthreads();
#pragma unroll
        for (int jj = 0; jj < 4; ++jj)
            sbuf[wid][jj * 32 + lane] = s[c * 4 + jj];
        __syncthreads();
        if (tid < 128) {
            float4 tot = sbuf[0][tid];
#pragma unroll
            for (int w = 1; w < NWARP; ++w) {
                float4 p = sbuf[w][tid];
                tot.x += p.x; tot.y += p.y; tot.z += p.z; tot.w += p.w;
            }
            ssq += (double)tot.x * (double)tot.x;
            ssq += (double)tot.y * (double)tot.y;
            ssq += (double)tot.z * (double)tot.z;
            ssq += (double)tot.w * (double)tot.w;
        }
    }

    // block-reduce ssq (upper 128 threads contribute 0)
#pragma unroll
    for (int o = 16; o > 0; o >>= 1)
        ssq += __shfl_xor_sync(0xffffffffu, ssq, o);
    if (lane == 0) dsm[wid] = ssq;
    __syncthreads();

    if (tid == 0) {
        double S = 0.0, Dg = 0.0;
#pragma unroll
        for (int w = 0; w < NWARP; ++w) { S += dsm[w]; Dg += dsm[NWARP + w]; }
        g_batch_loss[b] = S - Dg;
        __threadfence();
        s_ticket = atomicAdd(&g_done, 1u);
    }
    __syncthreads();

    // last finishing block: deterministic fixed-order mean over batches
    if (s_ticket == B_BATCH - 1) {
        double v = (tid < B_BATCH) ? g_batch_loss[tid] : 0.0;
#pragma unroll
        for (int o = 16; o > 0; o >>= 1)
            v += __shfl_xor_sync(0xffffffffu, v, o);
        if (lane == 0) dsm[wid] = v;
        __syncthreads();
        if (tid == 0) {
            double t = 0.0;
#pragma unroll
            for (int w = 0; w < 4; ++w) t += dsm[w];   // batches live in warps 0..3
            out[0] = (float)(t / (double)B_BATCH);
            g_done = 0;   // self-reset for graph replay
        }
    }
}

extern "C" void kernel_launch(void* const* d_in, const int* in_sizes, int n_in,
                              void* d_out, int out_size)
{
    (void)in_sizes; (void)n_in; (void)out_size;
    const float* in = (const float*)d_in[0];
    float* out = (float*)d_out;

    loss_fused_kernel<<<B_BATCH, NTHREADS>>>(in, out);
}